// round 1
// baseline (speedup 1.0000x reference)
#include <cuda_runtime.h>
#include <cstdint>

#define BB 256
#define NN 512
#define FF 128
#define HH 128
#define K1 256
#define K2 128
#define NT (BB*NN)

// ---------------- device scratch (static, zero-init; atomically-filled buffers are self-cleaning) ----------------
__device__ float g_h[(size_t)NT*HH];        // x@W1, then relu(gcn) in-place
__device__ float g_acc[(size_t)NT*HH];      // agg then smooth (self-clean)
__device__ int   g_deg[NT];                 // self-clean
__device__ float g_dinv1[NT];
__device__ float g_dinv2[NT];
__device__ float g_s1[NT];
__device__ int   g_keep[NT];
__device__ int   g_idx1[BB*K1];
__device__ float g_hk[(size_t)BB*K1*HH];
__device__ float g_Akb[(size_t)BB*K1*K1];   // pooled adjacency counts (self-clean)
__device__ float g_A1[(size_t)BB*K1*K1];
__device__ float g_q1[BB*K1], g_sv1[BB*K1], g_rowA1[BB*K1];
__device__ float g_hw[(size_t)BB*K1*HH];
__device__ float g_tmp[(size_t)BB*K1*HH];
__device__ float g_h2[(size_t)BB*K1*HH];
__device__ float g_h2s[(size_t)BB*K1*HH];
__device__ float g_tmp2[(size_t)BB*K1*HH];
__device__ float g_s2[BB*K1];
__device__ int   g_idx2[BB*K2];
__device__ float g_h2k[(size_t)BB*K2*HH];
__device__ float g_A2[(size_t)BB*K2*K2];
__device__ float g_q2[BB*K2], g_sv2[BB*K2], g_rowA2[BB*K2];
__device__ float g_hw3[(size_t)BB*K2*HH];
__device__ float g_tmp3[(size_t)BB*K2*HH];
__device__ float g_h3[(size_t)BB*K2*HH];

// ---------------- kernels ----------------

__global__ void k_deg(const int* __restrict__ dst, int E) {
    int e = blockIdx.x * blockDim.x + threadIdx.x;
    if (e < E) atomicAdd(&g_deg[dst[e]], 1);
}

__global__ void k_dinv() {
    int i = blockIdx.x * blockDim.x + threadIdx.x;
    if (i >= NT) return;
    int d = g_deg[i];
    g_deg[i] = 0;                               // self-clean
    g_dinv1[i] = rsqrtf((float)d + 1.0f);
    g_dinv2[i] = d > 0 ? rsqrtf((float)d) : 0.0f;
}

// Generic fp32 GEMM, N fixed at 128 cols. C[M,128] = A[M,K] @ B[K,128], batched via blockIdx.z.
__global__ __launch_bounds__(256) void k_gemm128(
    const float* __restrict__ A, const float* __restrict__ Bm, float* __restrict__ C,
    int M, int K, long long sA, long long sB, long long sC)
{
    const float* Ab = A + (size_t)blockIdx.z * sA;
    const float* Bb = Bm + (size_t)blockIdx.z * sB;
    float* Cb = C + (size_t)blockIdx.z * sC;
    int m0 = blockIdx.y * 64;
    __shared__ float As[64][33];
    __shared__ float Bs[32][132];
    int tid = threadIdx.x;
    int rt = tid >> 4, ct = tid & 15;
    float acc[4][8];
#pragma unroll
    for (int r = 0; r < 4; r++)
#pragma unroll
        for (int j = 0; j < 8; j++) acc[r][j] = 0.f;

    for (int k0 = 0; k0 < K; k0 += 32) {
#pragma unroll
        for (int l = 0; l < 8; l++) {
            int idx = tid + l * 256;
            int r = idx >> 5, c = idx & 31;
            As[r][c] = Ab[(size_t)(m0 + r) * K + k0 + c];
        }
#pragma unroll
        for (int l = 0; l < 16; l++) {
            int idx = tid + l * 256;
            int r = idx >> 7, c = idx & 127;
            Bs[r][c] = Bb[(size_t)(k0 + r) * 128 + c];
        }
        __syncthreads();
#pragma unroll
        for (int kk = 0; kk < 32; kk++) {
            float a0 = As[rt*4+0][kk], a1 = As[rt*4+1][kk], a2 = As[rt*4+2][kk], a3 = As[rt*4+3][kk];
#pragma unroll
            for (int j = 0; j < 8; j++) {
                float bv = Bs[kk][ct + 16*j];
                acc[0][j] += a0*bv; acc[1][j] += a1*bv; acc[2][j] += a2*bv; acc[3][j] += a3*bv;
            }
        }
        __syncthreads();
    }
#pragma unroll
    for (int r = 0; r < 4; r++)
#pragma unroll
        for (int j = 0; j < 8; j++)
            Cb[(size_t)(m0 + rt*4 + r) * 128 + ct + 16*j] = acc[r][j];
}

// One warp per edge: out[dst] += feat[src] * dinv[src]*dinv[dst]
__global__ void k_scatter(const int* __restrict__ src, const int* __restrict__ dst, int E,
                          const float* __restrict__ feat, const float* __restrict__ dinv,
                          float* __restrict__ out)
{
    int w = (blockIdx.x * blockDim.x + threadIdx.x) >> 5;
    if (w >= E) return;
    int lane = threadIdx.x & 31;
    int s = src[w], d = dst[w];
    float coef = dinv[s] * dinv[d];
    float4 v = ((const float4*)(feat + (size_t)s * HH))[lane];
    float* o = out + (size_t)d * HH + lane * 4;
    atomicAdd(o + 0, v.x * coef);
    atomicAdd(o + 1, v.y * coef);
    atomicAdd(o + 2, v.z * coef);
    atomicAdd(o + 3, v.w * coef);
}

__global__ void k_combine1(const float* __restrict__ b1) {
    size_t idx = (size_t)blockIdx.x * blockDim.x + threadIdx.x;
    if (idx >= (size_t)NT * HH) return;
    int n = (int)(idx >> 7), f = (int)(idx & 127);
    float a = g_acc[idx];
    g_acc[idx] = 0.f;                           // self-clean for smooth pass
    float di = g_dinv1[n];
    float v = a + g_h[idx] * di * di + b1[f];
    g_h[idx] = fmaxf(v, 0.f);
}

__global__ void k_score1() {
    int n = (blockIdx.x * blockDim.x + threadIdx.x) >> 5;
    if (n >= NT) return;
    int lane = threadIdx.x & 31;
    size_t base = (size_t)n * HH + lane * 4;
    float4 hv = *(const float4*)&g_h[base];
    float4 sv = *(const float4*)&g_acc[base];
    *(float4*)&g_acc[base] = make_float4(0.f, 0.f, 0.f, 0.f);  // self-clean
    float s = fabsf(hv.x - sv.x) + fabsf(hv.y - sv.y) + fabsf(hv.z - sv.z) + fabsf(hv.w - sv.w);
#pragma unroll
    for (int o = 16; o > 0; o >>= 1) s += __shfl_down_sync(0xffffffffu, s, o);
    if (lane == 0) g_s1[n] = s;
}

// rank-count top-k selection, exactly matches lax.top_k set (ties broken by lower index)
__global__ void k_topk(const float* __restrict__ scores, int n, int k,
                       int* __restrict__ idx_out, int* __restrict__ keep)
{
    extern __shared__ float ss[];
    int g = blockIdx.x, i = threadIdx.x;
    float si = scores[(size_t)g * n + i];
    ss[i] = si;
    __syncthreads();
    int rank = 0;
    for (int j = 0; j < n; j++) {
        float sj = ss[j];
        rank += (sj > si) || (sj == si && j < i);
    }
    if (rank < k) idx_out[(size_t)g * k + rank] = i;
    if (keep) keep[(size_t)g * n + i] = (rank < k) ? rank : -1;
}

__global__ void k_gather(const float* __restrict__ src, const int* __restrict__ idx,
                         float* __restrict__ dst, int rowsPerG, int k)
{
    int w = (blockIdx.x * blockDim.x + threadIdx.x) >> 5;
    if (w >= BB * k) return;
    int lane = threadIdx.x & 31;
    int g = w / k;
    int i = idx[w];
    ((float4*)(dst + (size_t)w * HH))[lane] =
        ((const float4*)(src + ((size_t)g * rowsPerG + i) * HH))[lane];
}

__global__ void k_edgeAk(const int* __restrict__ src, const int* __restrict__ dst, int E) {
    int e = blockIdx.x * blockDim.x + threadIdx.x;
    if (e >= E) return;
    int s = src[e];
    int rs = g_keep[s];
    if (rs < 0) return;
    int d = dst[e];
    int rd = g_keep[d];
    if (rd < 0) return;
    int g = s >> 9;   // N = 512
    atomicAdd(&g_Akb[((size_t)g * K1 + rs) * K1 + rd], 1.0f);
}

__global__ void k_qs(const float* __restrict__ feat, const float* __restrict__ att,
                     float* __restrict__ q, float* __restrict__ s, int rows)
{
    int w = (blockIdx.x * blockDim.x + threadIdx.x) >> 5;
    if (w >= rows) return;
    int lane = threadIdx.x & 31;
    float4 h4 = ((const float4*)(feat + (size_t)w * HH))[lane];
    float4 a4 = ((const float4*)att)[lane];
    float4 b4 = ((const float4*)att)[32 + lane];
    float qd = h4.x*a4.x + h4.y*a4.y + h4.z*a4.z + h4.w*a4.w;
    float sd = h4.x*b4.x + h4.y*b4.y + h4.z*b4.z + h4.w*b4.w;
#pragma unroll
    for (int o = 16; o > 0; o >>= 1) {
        qd += __shfl_down_sync(0xffffffffu, qd, o);
        sd += __shfl_down_sync(0xffffffffu, sd, o);
    }
    if (lane == 0) { q[w] = qd; s[w] = sd; }
}

// structure learning: A = softmax(leaky(q_i + s_j)) + Ak ; also emits rowsum(Ak)
template <int KDIM, int MODE>
__global__ void k_struct() {
    int row = blockIdx.x;                    // g*KDIM + i
    int g = row / KDIM;
    int j = threadIdx.x;
    __shared__ float red[KDIM];
    float qi = (MODE == 0 ? g_q1 : g_q2)[row];
    float sj = (MODE == 0 ? g_sv1 : g_sv2)[(size_t)g * KDIM + j];
    float v = qi + sj;
    v = v > 0.f ? v : 0.2f * v;              // leaky relu
    red[j] = v; __syncthreads();
    for (int st = KDIM / 2; st > 0; st >>= 1) {
        if (j < st) red[j] = fmaxf(red[j], red[j + st]);
        __syncthreads();
    }
    float vmax = red[0]; __syncthreads();
    float e = __expf(v - vmax);
    red[j] = e; __syncthreads();
    for (int st = KDIM / 2; st > 0; st >>= 1) {
        if (j < st) red[j] += red[j + st];
        __syncthreads();
    }
    float esum = red[0]; __syncthreads();
    float ak;
    if (MODE == 0) {
        size_t off = (size_t)row * K1 + j;
        ak = g_Akb[off];
        g_Akb[off] = 0.f;                    // self-clean
    } else {
        int ig = g_idx2[row];
        int jg = g_idx2[g * K2 + j];
        ak = g_A1[((size_t)g * K1 + ig) * K1 + jg];
    }
    (MODE == 0 ? g_A1 : g_A2)[(size_t)row * KDIM + j] = e / esum + ak;
    red[j] = ak; __syncthreads();
    for (int st = KDIM / 2; st > 0; st >>= 1) {
        if (j < st) red[j] += red[j + st];
        __syncthreads();
    }
    if (j == 0) (MODE == 0 ? g_rowA1 : g_rowA2)[row] = red[0];
}

__global__ void k_readout(const float* __restrict__ feat, int k, float* __restrict__ out, int accumulate) {
    int g = blockIdx.x, f = threadIdx.x;     // 128 threads
    float mx = -1e30f, sm = 0.f;
    const float* p = feat + (size_t)g * k * HH + f;
    for (int n = 0; n < k; n++) {
        float v = p[(size_t)n * HH];
        mx = fmaxf(mx, v);
        sm += v;
    }
    float o0 = fmaxf(mx, 0.f);
    float o1 = fmaxf(sm / (float)k, 0.f);
    if (accumulate) { out[g * 256 + f] += o0; out[g * 256 + 128 + f] += o1; }
    else            { out[g * 256 + f]  = o0; out[g * 256 + 128 + f]  = o1; }
}

__global__ void k_scale_copy(const float* __restrict__ src, float* __restrict__ dst,
                             const float* __restrict__ rowA, float add, size_t total) {
    size_t idx = (size_t)blockIdx.x * blockDim.x + threadIdx.x;
    if (idx >= total) return;
    int row = (int)(idx >> 7);
    float d = rsqrtf(fmaxf(rowA[row] + add, 1e-12f));
    dst[idx] = src[idx] * d;
}

__global__ void k_combine2(const float* __restrict__ tmp, const float* __restrict__ hws,
                           const float* __restrict__ rowA, const float* __restrict__ bias,
                           float* __restrict__ out, size_t total) {
    size_t idx = (size_t)blockIdx.x * blockDim.x + threadIdx.x;
    if (idx >= total) return;
    int row = (int)(idx >> 7), f = (int)(idx & 127);
    float di = rsqrtf(fmaxf(rowA[row] + 2.0f, 1e-12f));
    out[idx] = fmaxf(di * (tmp[idx] + hws[idx]) + bias[f], 0.f);
}

__global__ void k_score2(const float* __restrict__ h2, const float* __restrict__ tmp2,
                         const float* __restrict__ rowA, float* __restrict__ sc, int rows) {
    int w = (blockIdx.x * blockDim.x + threadIdx.x) >> 5;
    if (w >= rows) return;
    int lane = threadIdx.x & 31;
    float d = rsqrtf(fmaxf(rowA[w] + 1.0f, 1e-12f));
    size_t base = (size_t)w * HH + lane * 4;
    float4 hv = *(const float4*)&h2[base];
    float4 tv = *(const float4*)&tmp2[base];
    float s = fabsf(hv.x - d*tv.x) + fabsf(hv.y - d*tv.y) + fabsf(hv.z - d*tv.z) + fabsf(hv.w - d*tv.w);
#pragma unroll
    for (int o = 16; o > 0; o >>= 1) s += __shfl_down_sync(0xffffffffu, s, o);
    if (lane == 0) sc[w] = s;
}

// ---------------- host ----------------

static float* symf(const void* sym) {
    void* p = nullptr;
    cudaGetSymbolAddress(&p, sym);
    return (float*)p;
}
static int* symi(const void* sym) {
    void* p = nullptr;
    cudaGetSymbolAddress(&p, sym);
    return (int*)p;
}

extern "C" void kernel_launch(void* const* d_in, const int* in_sizes, int n_in,
                              void* d_out, int out_size)
{
    const float* x    = (const float*)d_in[0];
    const float* W1   = (const float*)d_in[1];
    const float* b1   = (const float*)d_in[2];
    const float* W2   = (const float*)d_in[3];
    const float* b2   = (const float*)d_in[4];
    const float* W3   = (const float*)d_in[5];
    const float* b3   = (const float*)d_in[6];
    const float* att1 = (const float*)d_in[7];
    const float* att2 = (const float*)d_in[8];
    const int* esrc   = (const int*)d_in[9];
    const int* edst   = (const int*)d_in[10];
    int E = in_sizes[9];
    float* out = (float*)d_out;

    float* p_h    = symf(g_h);
    float* p_acc  = symf(g_acc);
    float* p_d1   = symf(g_dinv1);
    float* p_d2   = symf(g_dinv2);
    float* p_s1   = symf(g_s1);
    int*   p_keep = symi(g_keep);
    int*   p_idx1 = symi(g_idx1);
    float* p_hk   = symf(g_hk);
    float* p_A1   = symf(g_A1);
    float* p_q1   = symf(g_q1);
    float* p_sv1  = symf(g_sv1);
    float* p_rA1  = symf(g_rowA1);
    float* p_hw   = symf(g_hw);
    float* p_tmp  = symf(g_tmp);
    float* p_h2   = symf(g_h2);
    float* p_h2s  = symf(g_h2s);
    float* p_tmp2 = symf(g_tmp2);
    float* p_s2   = symf(g_s2);
    int*   p_idx2 = symi(g_idx2);
    float* p_h2k  = symf(g_h2k);
    float* p_A2   = symf(g_A2);
    float* p_q2   = symf(g_q2);
    float* p_sv2  = symf(g_sv2);
    float* p_rA2  = symf(g_rowA2);
    float* p_hw3  = symf(g_hw3);
    float* p_tmp3 = symf(g_tmp3);
    float* p_h3   = symf(g_h3);

    const size_t T1 = (size_t)NT * HH;             // 16.7M
    const size_t T2 = (size_t)BB * K1 * HH;        // 8.4M
    const size_t T3 = (size_t)BB * K2 * HH;        // 4.2M

    // ---- stage 1: edge GCN + info score ----
    k_deg<<<(E + 255) / 256, 256>>>(edst, E);
    k_gemm128<<<dim3(1, NT / 64, 1), 256>>>(x, W1, p_h, NT, FF, 0, 0, 0);
    k_dinv<<<(NT + 255) / 256, 256>>>();
    k_scatter<<<(unsigned)(((size_t)E * 32 + 255) / 256), 256>>>(esrc, edst, E, p_h, p_d1, p_acc);
    k_combine1<<<(unsigned)((T1 + 255) / 256), 256>>>(b1);
    k_scatter<<<(unsigned)(((size_t)E * 32 + 255) / 256), 256>>>(esrc, edst, E, p_h, p_d2, p_acc);
    k_score1<<<(NT * 32 + 255) / 256, 256>>>();

    // ---- pool 1 ----
    k_topk<<<BB, NN, NN * sizeof(float)>>>(p_s1, NN, K1, p_idx1, p_keep);
    k_gather<<<(BB * K1 * 32 + 255) / 256, 256>>>(p_h, p_idx1, p_hk, NN, K1);
    k_edgeAk<<<(E + 255) / 256, 256>>>(esrc, edst, E);
    k_qs<<<(BB * K1 * 32 + 255) / 256, 256>>>(p_hk, att1, p_q1, p_sv1, BB * K1);
    k_struct<K1, 0><<<BB * K1, K1>>>();
    k_readout<<<BB, 128>>>(p_hk, K1, out, 0);

    // ---- conv2 (dense GCN on A1) ----
    k_gemm128<<<dim3(1, K1 / 64, BB), 256>>>(p_hk, W2, p_hw, K1, HH,
                                             (long long)K1 * HH, 0, (long long)K1 * HH);
    k_scale_copy<<<(unsigned)((T2 + 255) / 256), 256>>>(p_hw, p_hw, p_rA1, 2.0f, T2);
    k_gemm128<<<dim3(1, K1 / 64, BB), 256>>>(p_A1, p_hw, p_tmp, K1, K1,
                                             (long long)K1 * K1, (long long)K1 * HH, (long long)K1 * HH);
    k_combine2<<<(unsigned)((T2 + 255) / 256), 256>>>(p_tmp, p_hw, p_rA1, b2, p_h2, T2);

    // ---- info score 2 ----
    k_scale_copy<<<(unsigned)((T2 + 255) / 256), 256>>>(p_h2, p_h2s, p_rA1, 1.0f, T2);
    k_gemm128<<<dim3(1, K1 / 64, BB), 256>>>(p_A1, p_h2s, p_tmp2, K1, K1,
                                             (long long)K1 * K1, (long long)K1 * HH, (long long)K1 * HH);
    k_score2<<<(BB * K1 * 32 + 255) / 256, 256>>>(p_h2, p_tmp2, p_rA1, p_s2, BB * K1);

    // ---- pool 2 ----
    k_topk<<<BB, K1, K1 * sizeof(float)>>>(p_s2, K1, K2, p_idx2, nullptr);
    k_gather<<<(BB * K2 * 32 + 255) / 256, 256>>>(p_h2, p_idx2, p_h2k, K1, K2);
    k_qs<<<(BB * K2 * 32 + 255) / 256, 256>>>(p_h2k, att2, p_q2, p_sv2, BB * K2);
    k_struct<K2, 1><<<BB * K2, K2>>>();
    k_readout<<<BB, 128>>>(p_h2k, K2, out, 1);

    // ---- conv3 ----
    k_gemm128<<<dim3(1, K2 / 64, BB), 256>>>(p_h2k, W3, p_hw3, K2, HH,
                                             (long long)K2 * HH, 0, (long long)K2 * HH);
    k_scale_copy<<<(unsigned)((T3 + 255) / 256), 256>>>(p_hw3, p_hw3, p_rA2, 2.0f, T3);
    k_gemm128<<<dim3(1, K2 / 64, BB), 256>>>(p_A2, p_hw3, p_tmp3, K2, K2,
                                             (long long)K2 * K2, (long long)K2 * HH, (long long)K2 * HH);
    k_combine2<<<(unsigned)((T3 + 255) / 256), 256>>>(p_tmp3, p_hw3, p_rA2, b3, p_h3, T3);
    k_readout<<<BB, 128>>>(p_h3, K2, out, 1);
}

// round 2
// speedup vs baseline: 2.1825x; 2.1825x over previous
#include <cuda_runtime.h>
#include <cstdint>

#define BB 256
#define NN 512
#define FF 128
#define HH 128
#define K1 256
#define K2 128
#define NT (BB*NN)
#define EMAX (BB*NN*16)

// ---------------- device scratch ----------------
__device__ float g_h[(size_t)NT*HH];        // x@W1
__device__ float g_hr[(size_t)NT*HH];       // relu(gcn1)
__device__ int   g_deg[NT];                 // self-clean
__device__ int   g_offs[NT];
__device__ int   g_cur[NT];
__device__ int   g_csr[EMAX];
__device__ float g_dinv1[NT];
__device__ float g_dinv2[NT];
__device__ float g_s1[NT];
__device__ int   g_keep[NT];
__device__ int   g_idx1[BB*K1];
__device__ float g_hk[(size_t)BB*K1*HH];
__device__ float g_Akb[(size_t)BB*K1*K1];   // pooled adjacency counts (self-clean)
__device__ float g_A1[(size_t)BB*K1*K1];
__device__ float g_q1[BB*K1], g_sv1[BB*K1], g_rowA1[BB*K1];
__device__ float g_hw[(size_t)BB*K1*HH];
__device__ float g_tmp[(size_t)BB*K1*HH];
__device__ float g_h2[(size_t)BB*K1*HH];
__device__ float g_h2s[(size_t)BB*K1*HH];
__device__ float g_tmp2[(size_t)BB*K1*HH];
__device__ float g_s2[BB*K1];
__device__ int   g_idx2[BB*K2];
__device__ float g_h2k[(size_t)BB*K2*HH];
__device__ float g_A2[(size_t)BB*K2*K2];
__device__ float g_q2[BB*K2], g_sv2[BB*K2], g_rowA2[BB*K2];
__device__ float g_hw3[(size_t)BB*K2*HH];
__device__ float g_tmp3[(size_t)BB*K2*HH];
__device__ float g_h3[(size_t)BB*K2*HH];

// ---------------- kernels ----------------

__global__ void k_deg(const int* __restrict__ dst, int E) {
    int e = blockIdx.x * blockDim.x + threadIdx.x;
    if (e < E) atomicAdd(&g_deg[dst[e]], 1);
}

// per-graph inclusive scan over 512 node degrees -> CSR offsets; also dinv + deg self-clean
__global__ void k_scan(int eper) {
    __shared__ int sh[NN];
    int g = blockIdx.x, i = threadIdx.x;
    int n = g * NN + i;
    int d = g_deg[n];
    g_deg[n] = 0;                               // self-clean
    g_dinv1[n] = rsqrtf((float)d + 1.0f);
    g_dinv2[n] = d > 0 ? rsqrtf((float)d) : 0.0f;
    sh[i] = d; __syncthreads();
#pragma unroll
    for (int off = 1; off < NN; off <<= 1) {
        int v = (i >= off) ? sh[i - off] : 0;
        __syncthreads();
        sh[i] += v;
        __syncthreads();
    }
    int o = g * eper + sh[i] - d;               // exclusive prefix
    g_offs[n] = o;
    g_cur[n] = o;
}

__global__ void k_fill(const int* __restrict__ src, const int* __restrict__ dst, int E) {
    int e = blockIdx.x * blockDim.x + threadIdx.x;
    if (e >= E) return;
    int pos = atomicAdd(&g_cur[dst[e]], 1);
    g_csr[pos] = src[e];
}

// fused GCN aggregation: out[n] = relu( sum_in dinv1[s]*dinv1[n]*feat[s] + feat[n]*dinv1[n]^2 + b )
__global__ void k_agg1(const float* __restrict__ feat, const float* __restrict__ bias,
                       float* __restrict__ out)
{
    int n = (blockIdx.x * blockDim.x + threadIdx.x) >> 5;
    if (n >= NT) return;
    int lane = threadIdx.x & 31;
    int e0 = g_offs[n], e1 = g_cur[n];
    float dd = g_dinv1[n];
    float ax = 0.f, ay = 0.f, az = 0.f, aw = 0.f;
    for (int e = e0; e < e1; e++) {
        int s = g_csr[e];
        float c = g_dinv1[s] * dd;
        float4 v = ((const float4*)feat)[(size_t)s * 32 + lane];
        ax += v.x * c; ay += v.y * c; az += v.z * c; aw += v.w * c;
    }
    float4 hv = ((const float4*)feat)[(size_t)n * 32 + lane];
    float sc = dd * dd;
    float4 b4 = ((const float4*)bias)[lane];
    float4 o;
    o.x = fmaxf(ax + hv.x * sc + b4.x, 0.f);
    o.y = fmaxf(ay + hv.y * sc + b4.y, 0.f);
    o.z = fmaxf(az + hv.z * sc + b4.z, 0.f);
    o.w = fmaxf(aw + hv.w * sc + b4.w, 0.f);
    ((float4*)out)[(size_t)n * 32 + lane] = o;
}

// fused smooth + L1 info score: s1[n] = sum_f |feat[n,f] - sum_in dinv2[s]*dinv2[n]*feat[s,f]|
__global__ void k_aggscore(const float* __restrict__ feat)
{
    int n = (blockIdx.x * blockDim.x + threadIdx.x) >> 5;
    if (n >= NT) return;
    int lane = threadIdx.x & 31;
    int e0 = g_offs[n], e1 = g_cur[n];
    float dd = g_dinv2[n];
    float ax = 0.f, ay = 0.f, az = 0.f, aw = 0.f;
    for (int e = e0; e < e1; e++) {
        int s = g_csr[e];
        float c = g_dinv2[s] * dd;
        float4 v = ((const float4*)feat)[(size_t)s * 32 + lane];
        ax += v.x * c; ay += v.y * c; az += v.z * c; aw += v.w * c;
    }
    float4 hv = ((const float4*)feat)[(size_t)n * 32 + lane];
    float s = fabsf(hv.x - ax) + fabsf(hv.y - ay) + fabsf(hv.z - az) + fabsf(hv.w - aw);
#pragma unroll
    for (int o = 16; o > 0; o >>= 1) s += __shfl_down_sync(0xffffffffu, s, o);
    if (lane == 0) g_s1[n] = s;
}

// Generic fp32 GEMM, N fixed at 128 cols. C[M,128] = A[M,K] @ B[K,128], batched via blockIdx.z.
__global__ __launch_bounds__(256) void k_gemm128(
    const float* __restrict__ A, const float* __restrict__ Bm, float* __restrict__ C,
    int M, int K, long long sA, long long sB, long long sC)
{
    const float* Ab = A + (size_t)blockIdx.z * sA;
    const float* Bb = Bm + (size_t)blockIdx.z * sB;
    float* Cb = C + (size_t)blockIdx.z * sC;
    int m0 = blockIdx.y * 64;
    __shared__ float As[64][33];
    __shared__ float Bs[32][132];
    int tid = threadIdx.x;
    int rt = tid >> 4, ct = tid & 15;
    float acc[4][8];
#pragma unroll
    for (int r = 0; r < 4; r++)
#pragma unroll
        for (int j = 0; j < 8; j++) acc[r][j] = 0.f;

    for (int k0 = 0; k0 < K; k0 += 32) {
#pragma unroll
        for (int l = 0; l < 8; l++) {
            int idx = tid + l * 256;
            int r = idx >> 5, c = idx & 31;
            As[r][c] = Ab[(size_t)(m0 + r) * K + k0 + c];
        }
#pragma unroll
        for (int l = 0; l < 16; l++) {
            int idx = tid + l * 256;
            int r = idx >> 7, c = idx & 127;
            Bs[r][c] = Bb[(size_t)(k0 + r) * 128 + c];
        }
        __syncthreads();
#pragma unroll
        for (int kk = 0; kk < 32; kk++) {
            float a0 = As[rt*4+0][kk], a1 = As[rt*4+1][kk], a2 = As[rt*4+2][kk], a3 = As[rt*4+3][kk];
#pragma unroll
            for (int j = 0; j < 8; j++) {
                float bv = Bs[kk][ct + 16*j];
                acc[0][j] += a0*bv; acc[1][j] += a1*bv; acc[2][j] += a2*bv; acc[3][j] += a3*bv;
            }
        }
        __syncthreads();
    }
#pragma unroll
    for (int r = 0; r < 4; r++)
#pragma unroll
        for (int j = 0; j < 8; j++)
            Cb[(size_t)(m0 + rt*4 + r) * 128 + ct + 16*j] = acc[r][j];
}

// rank-count top-k selection, exactly matches lax.top_k set (ties broken by lower index)
__global__ void k_topk(const float* __restrict__ scores, int n, int k,
                       int* __restrict__ idx_out, int* __restrict__ keep)
{
    extern __shared__ float ss[];
    int g = blockIdx.x, i = threadIdx.x;
    float si = scores[(size_t)g * n + i];
    ss[i] = si;
    __syncthreads();
    int rank = 0;
    for (int j = 0; j < n; j++) {
        float sj = ss[j];
        rank += (sj > si) || (sj == si && j < i);
    }
    if (rank < k) idx_out[(size_t)g * k + rank] = i;
    if (keep) keep[(size_t)g * n + i] = (rank < k) ? rank : -1;
}

__global__ void k_gather(const float* __restrict__ src, const int* __restrict__ idx,
                         float* __restrict__ dst, int rowsPerG, int k)
{
    int w = (blockIdx.x * blockDim.x + threadIdx.x) >> 5;
    if (w >= BB * k) return;
    int lane = threadIdx.x & 31;
    int g = w / k;
    int i = idx[w];
    ((float4*)(dst + (size_t)w * HH))[lane] =
        ((const float4*)(src + ((size_t)g * rowsPerG + i) * HH))[lane];
}

__global__ void k_edgeAk(const int* __restrict__ src, const int* __restrict__ dst, int E) {
    int e = blockIdx.x * blockDim.x + threadIdx.x;
    if (e >= E) return;
    int s = src[e];
    int rs = g_keep[s];
    if (rs < 0) return;
    int d = dst[e];
    int rd = g_keep[d];
    if (rd < 0) return;
    int g = s >> 9;   // N = 512
    atomicAdd(&g_Akb[((size_t)g * K1 + rs) * K1 + rd], 1.0f);
}

__global__ void k_qs(const float* __restrict__ feat, const float* __restrict__ att,
                     float* __restrict__ q, float* __restrict__ s, int rows)
{
    int w = (blockIdx.x * blockDim.x + threadIdx.x) >> 5;
    if (w >= rows) return;
    int lane = threadIdx.x & 31;
    float4 h4 = ((const float4*)(feat + (size_t)w * HH))[lane];
    float4 a4 = ((const float4*)att)[lane];
    float4 b4 = ((const float4*)att)[32 + lane];
    float qd = h4.x*a4.x + h4.y*a4.y + h4.z*a4.z + h4.w*a4.w;
    float sd = h4.x*b4.x + h4.y*b4.y + h4.z*b4.z + h4.w*b4.w;
#pragma unroll
    for (int o = 16; o > 0; o >>= 1) {
        qd += __shfl_down_sync(0xffffffffu, qd, o);
        sd += __shfl_down_sync(0xffffffffu, sd, o);
    }
    if (lane == 0) { q[w] = qd; s[w] = sd; }
}

// structure learning: A = softmax(leaky(q_i + s_j)) + Ak ; also emits rowsum(Ak)
template <int KDIM, int MODE>
__global__ void k_struct() {
    int row = blockIdx.x;                    // g*KDIM + i
    int g = row / KDIM;
    int j = threadIdx.x;
    __shared__ float red[KDIM];
    float qi = (MODE == 0 ? g_q1 : g_q2)[row];
    float sj = (MODE == 0 ? g_sv1 : g_sv2)[(size_t)g * KDIM + j];
    float v = qi + sj;
    v = v > 0.f ? v : 0.2f * v;              // leaky relu
    red[j] = v; __syncthreads();
    for (int st = KDIM / 2; st > 0; st >>= 1) {
        if (j < st) red[j] = fmaxf(red[j], red[j + st]);
        __syncthreads();
    }
    float vmax = red[0]; __syncthreads();
    float e = __expf(v - vmax);
    red[j] = e; __syncthreads();
    for (int st = KDIM / 2; st > 0; st >>= 1) {
        if (j < st) red[j] += red[j + st];
        __syncthreads();
    }
    float esum = red[0]; __syncthreads();
    float ak;
    if (MODE == 0) {
        size_t off = (size_t)row * K1 + j;
        ak = g_Akb[off];
        g_Akb[off] = 0.f;                    // self-clean
    } else {
        int ig = g_idx2[row];
        int jg = g_idx2[g * K2 + j];
        ak = g_A1[((size_t)g * K1 + ig) * K1 + jg];
    }
    (MODE == 0 ? g_A1 : g_A2)[(size_t)row * KDIM + j] = e / esum + ak;
    red[j] = ak; __syncthreads();
    for (int st = KDIM / 2; st > 0; st >>= 1) {
        if (j < st) red[j] += red[j + st];
        __syncthreads();
    }
    if (j == 0) (MODE == 0 ? g_rowA1 : g_rowA2)[row] = red[0];
}

__global__ void k_readout(const float* __restrict__ feat, int k, float* __restrict__ out, int accumulate) {
    int g = blockIdx.x, f = threadIdx.x;     // 128 threads
    float mx = -1e30f, sm = 0.f;
    const float* p = feat + (size_t)g * k * HH + f;
    for (int n = 0; n < k; n++) {
        float v = p[(size_t)n * HH];
        mx = fmaxf(mx, v);
        sm += v;
    }
    float o0 = fmaxf(mx, 0.f);
    float o1 = fmaxf(sm / (float)k, 0.f);
    if (accumulate) { out[g * 256 + f] += o0; out[g * 256 + 128 + f] += o1; }
    else            { out[g * 256 + f]  = o0; out[g * 256 + 128 + f]  = o1; }
}

__global__ void k_scale_copy(const float* __restrict__ src, float* __restrict__ dst,
                             const float* __restrict__ rowA, float add, size_t total) {
    size_t idx = (size_t)blockIdx.x * blockDim.x + threadIdx.x;
    if (idx >= total) return;
    int row = (int)(idx >> 7);
    float d = rsqrtf(fmaxf(rowA[row] + add, 1e-12f));
    dst[idx] = src[idx] * d;
}

__global__ void k_combine2(const float* __restrict__ tmp, const float* __restrict__ hws,
                           const float* __restrict__ rowA, const float* __restrict__ bias,
                           float* __restrict__ out, size_t total) {
    size_t idx = (size_t)blockIdx.x * blockDim.x + threadIdx.x;
    if (idx >= total) return;
    int row = (int)(idx >> 7), f = (int)(idx & 127);
    float di = rsqrtf(fmaxf(rowA[row] + 2.0f, 1e-12f));
    out[idx] = fmaxf(di * (tmp[idx] + hws[idx]) + bias[f], 0.f);
}

__global__ void k_score2(const float* __restrict__ h2, const float* __restrict__ tmp2,
                         const float* __restrict__ rowA, float* __restrict__ sc, int rows) {
    int w = (blockIdx.x * blockDim.x + threadIdx.x) >> 5;
    if (w >= rows) return;
    int lane = threadIdx.x & 31;
    float d = rsqrtf(fmaxf(rowA[w] + 1.0f, 1e-12f));
    size_t base = (size_t)w * HH + lane * 4;
    float4 hv = *(const float4*)&h2[base];
    float4 tv = *(const float4*)&tmp2[base];
    float s = fabsf(hv.x - d*tv.x) + fabsf(hv.y - d*tv.y) + fabsf(hv.z - d*tv.z) + fabsf(hv.w - d*tv.w);
#pragma unroll
    for (int o = 16; o > 0; o >>= 1) s += __shfl_down_sync(0xffffffffu, s, o);
    if (lane == 0) sc[w] = s;
}

// ---------------- host ----------------

static float* symf(const void* sym) {
    void* p = nullptr;
    cudaGetSymbolAddress(&p, sym);
    return (float*)p;
}
static int* symi(const void* sym) {
    void* p = nullptr;
    cudaGetSymbolAddress(&p, sym);
    return (int*)p;
}

extern "C" void kernel_launch(void* const* d_in, const int* in_sizes, int n_in,
                              void* d_out, int out_size)
{
    const float* x    = (const float*)d_in[0];
    const float* W1   = (const float*)d_in[1];
    const float* b1   = (const float*)d_in[2];
    const float* W2   = (const float*)d_in[3];
    const float* b2   = (const float*)d_in[4];
    const float* W3   = (const float*)d_in[5];
    const float* b3   = (const float*)d_in[6];
    const float* att1 = (const float*)d_in[7];
    const float* att2 = (const float*)d_in[8];
    const int* esrc   = (const int*)d_in[9];
    const int* edst   = (const int*)d_in[10];
    int E = in_sizes[9];
    int eper = E / BB;
    float* out = (float*)d_out;

    float* p_h    = symf(g_h);
    float* p_hr   = symf(g_hr);
    float* p_s1   = symf(g_s1);
    int*   p_idx1 = symi(g_idx1);
    int*   p_keep = symi(g_keep);
    float* p_hk   = symf(g_hk);
    float* p_A1   = symf(g_A1);
    float* p_q1   = symf(g_q1);
    float* p_sv1  = symf(g_sv1);
    float* p_rA1  = symf(g_rowA1);
    float* p_hw   = symf(g_hw);
    float* p_tmp  = symf(g_tmp);
    float* p_h2   = symf(g_h2);
    float* p_h2s  = symf(g_h2s);
    float* p_tmp2 = symf(g_tmp2);
    float* p_s2   = symf(g_s2);
    int*   p_idx2 = symi(g_idx2);
    float* p_h2k  = symf(g_h2k);
    float* p_A2   = symf(g_A2);
    float* p_q2   = symf(g_q2);
    float* p_sv2  = symf(g_sv2);
    float* p_rA2  = symf(g_rowA2);
    float* p_hw3  = symf(g_hw3);
    float* p_tmp3 = symf(g_tmp3);
    float* p_h3   = symf(g_h3);

    const size_t T2 = (size_t)BB * K1 * HH;
    const size_t T3 = (size_t)BB * K2 * HH;

    // ---- stage 1: CSR build + edge GCN + info score (gather form, no feature atomics) ----
    k_deg<<<(E + 255) / 256, 256>>>(edst, E);
    k_gemm128<<<dim3(1, NT / 64, 1), 256>>>(x, W1, p_h, NT, FF, 0, 0, 0);
    k_scan<<<BB, NN>>>(eper);
    k_fill<<<(E + 255) / 256, 256>>>(esrc, edst, E);
    k_agg1<<<(NT * 32 + 255) / 256, 256>>>(p_h, b1, p_hr);
    k_aggscore<<<(NT * 32 + 255) / 256, 256>>>(p_hr);

    // ---- pool 1 ----
    k_topk<<<BB, NN, NN * sizeof(float)>>>(p_s1, NN, K1, p_idx1, p_keep);
    k_gather<<<(BB * K1 * 32 + 255) / 256, 256>>>(p_hr, p_idx1, p_hk, NN, K1);
    k_edgeAk<<<(E + 255) / 256, 256>>>(esrc, edst, E);
    k_qs<<<(BB * K1 * 32 + 255) / 256, 256>>>(p_hk, att1, p_q1, p_sv1, BB * K1);
    k_struct<K1, 0><<<BB * K1, K1>>>();
    k_readout<<<BB, 128>>>(p_hk, K1, out, 0);

    // ---- conv2 (dense GCN on A1) ----
    k_gemm128<<<dim3(1, K1 / 64, BB), 256>>>(p_hk, W2, p_hw, K1, HH,
                                             (long long)K1 * HH, 0, (long long)K1 * HH);
    k_scale_copy<<<(unsigned)((T2 + 255) / 256), 256>>>(p_hw, p_hw, p_rA1, 2.0f, T2);
    k_gemm128<<<dim3(1, K1 / 64, BB), 256>>>(p_A1, p_hw, p_tmp, K1, K1,
                                             (long long)K1 * K1, (long long)K1 * HH, (long long)K1 * HH);
    k_combine2<<<(unsigned)((T2 + 255) / 256), 256>>>(p_tmp, p_hw, p_rA1, b2, p_h2, T2);

    // ---- info score 2 ----
    k_scale_copy<<<(unsigned)((T2 + 255) / 256), 256>>>(p_h2, p_h2s, p_rA1, 1.0f, T2);
    k_gemm128<<<dim3(1, K1 / 64, BB), 256>>>(p_A1, p_h2s, p_tmp2, K1, K1,
                                             (long long)K1 * K1, (long long)K1 * HH, (long long)K1 * HH);
    k_score2<<<(BB * K1 * 32 + 255) / 256, 256>>>(p_h2, p_tmp2, p_rA1, p_s2, BB * K1);

    // ---- pool 2 ----
    k_topk<<<BB, K1, K1 * sizeof(float)>>>(p_s2, K1, K2, p_idx2, nullptr);
    k_gather<<<(BB * K2 * 32 + 255) / 256, 256>>>(p_h2, p_idx2, p_h2k, K1, K2);
    k_qs<<<(BB * K2 * 32 + 255) / 256, 256>>>(p_h2k, att2, p_q2, p_sv2, BB * K2);
    k_struct<K2, 1><<<BB * K2, K2>>>();
    k_readout<<<BB, 128>>>(p_h2k, K2, out, 1);

    // ---- conv3 ----
    k_gemm128<<<dim3(1, K2 / 64, BB), 256>>>(p_h2k, W3, p_hw3, K2, HH,
                                             (long long)K2 * HH, 0, (long long)K2 * HH);
    k_scale_copy<<<(unsigned)((T3 + 255) / 256), 256>>>(p_hw3, p_hw3, p_rA2, 2.0f, T3);
    k_gemm128<<<dim3(1, K2 / 64, BB), 256>>>(p_A2, p_hw3, p_tmp3, K2, K2,
                                             (long long)K2 * K2, (long long)K2 * HH, (long long)K2 * HH);
    k_combine2<<<(unsigned)((T3 + 255) / 256), 256>>>(p_tmp3, p_hw3, p_rA2, b3, p_h3, T3);
    k_readout<<<BB, 128>>>(p_h3, K2, out, 1);
}

// round 4
// speedup vs baseline: 2.3783x; 1.0897x over previous
#include <cuda_runtime.h>
#include <cstdint>

#define BB 256
#define NN 512
#define FF 128
#define HH 128
#define K1 256
#define K2 128
#define NT (BB*NN)
#define EMAX (BB*NN*16)

// ---------------- device scratch ----------------
__device__ float g_h[(size_t)NT*HH];        // x@W1
__device__ float g_hr[(size_t)NT*HH];       // relu(gcn1)
__device__ int   g_deg[NT];                 // self-clean
__device__ int   g_offs[NT];
__device__ int   g_cur[NT];
__device__ int   g_csr[EMAX];
__device__ float g_dinv1[NT];
__device__ float g_dinv2[NT];
__device__ float g_s1[NT];
__device__ int   g_keep[NT];
__device__ int   g_idx1[BB*K1];
__device__ float g_hk[(size_t)BB*K1*HH];
__device__ float g_Akb[(size_t)BB*K1*K1];   // pooled adjacency counts (self-clean)
__device__ float g_A1[(size_t)BB*K1*K1];
__device__ float g_q1[BB*K1], g_sv1[BB*K1], g_rowA1[BB*K1];
__device__ float g_hw[(size_t)BB*K1*HH];
__device__ float g_tmp[(size_t)BB*K1*HH];
__device__ float g_h2[(size_t)BB*K1*HH];
__device__ float g_h2s[(size_t)BB*K1*HH];
__device__ float g_tmp2[(size_t)BB*K1*HH];
__device__ float g_s2[BB*K1];
__device__ int   g_idx2[BB*K2];
__device__ float g_h2k[(size_t)BB*K2*HH];
__device__ float g_A2[(size_t)BB*K2*K2];
__device__ float g_q2[BB*K2], g_sv2[BB*K2], g_rowA2[BB*K2];
__device__ float g_hw3[(size_t)BB*K2*HH];
__device__ float g_tmp3[(size_t)BB*K2*HH];
__device__ float g_h3[(size_t)BB*K2*HH];

// ---------------- 3xTF32 mma.sync GEMM ----------------

#define ASTRIDE 36
#define BSTRIDE 136
// Ah[128][36] + Al + Bh[32][136] + Bl
#define GEMM_SMEM ((2*128*ASTRIDE + 2*32*BSTRIDE) * 4)

__device__ __forceinline__ float tf32r(float a) {
    uint32_t u;
    asm("cvt.rna.tf32.f32 %0, %1;" : "=r"(u) : "f"(a));
    return __uint_as_float(u);
}

#define MMA_TF32(d, a, b0, b1) \
    asm volatile("mma.sync.aligned.m16n8k8.row.col.f32.tf32.tf32.f32 " \
        "{%0,%1,%2,%3}, {%4,%5,%6,%7}, {%8,%9}, {%0,%1,%2,%3};" \
        : "+f"((d)[0]), "+f"((d)[1]), "+f"((d)[2]), "+f"((d)[3]) \
        : "r"((a)[0]), "r"((a)[1]), "r"((a)[2]), "r"((a)[3]), "r"(b0), "r"(b1))

// C[M,128] = A[M,K] @ B[K,128]; grid (1, M/128, batch); 256 threads.
// fp32-level precision via hi/lo tf32 split: 3 MMAs per fragment step.
__global__ __launch_bounds__(256) void k_gemm_mma(
    const float* __restrict__ A, const float* __restrict__ Bm, float* __restrict__ C,
    int M, int K, long long sA, long long sB, long long sC)
{
    extern __shared__ float sm[];
    float* Ah = sm;
    float* Al = Ah + 128 * ASTRIDE;
    float* Bh = Al + 128 * ASTRIDE;
    float* Bl = Bh + 32 * BSTRIDE;

    const float* Ab = A + (size_t)blockIdx.z * sA + (size_t)blockIdx.y * 128 * K;
    const float* Bb = Bm + (size_t)blockIdx.z * sB;
    float* Cb = C + (size_t)blockIdx.z * sC + (size_t)blockIdx.y * 128 * 128;

    const int tid = threadIdx.x;
    const int wid = tid >> 5, lane = tid & 31;
    const int wm = (wid >> 2) * 64, wn = (wid & 3) * 32;
    const int r = lane >> 2, cc = lane & 3;

    float acc[4][4][4];
#pragma unroll
    for (int i = 0; i < 4; i++)
#pragma unroll
        for (int j = 0; j < 4; j++)
#pragma unroll
            for (int q = 0; q < 4; q++) acc[i][j][q] = 0.f;

    const int nchunks = K >> 5;
    for (int c = 0; c < nchunks; c++) {
        const int k0 = c << 5;
        // stage A chunk 128x32, split hi/lo
#pragma unroll
        for (int i = 0; i < 4; i++) {
            int idx = tid + i * 256;            // 1024 float4s
            int m = idx >> 3, kq = idx & 7;
            float4 v = *(const float4*)&Ab[(size_t)m * K + k0 + kq * 4];
            float4 h, l;
            h.x = tf32r(v.x); l.x = tf32r(v.x - h.x);
            h.y = tf32r(v.y); l.y = tf32r(v.y - h.y);
            h.z = tf32r(v.z); l.z = tf32r(v.z - h.z);
            h.w = tf32r(v.w); l.w = tf32r(v.w - h.w);
            *(float4*)&Ah[m * ASTRIDE + kq * 4] = h;
            *(float4*)&Al[m * ASTRIDE + kq * 4] = l;
        }
        // stage B chunk 32x128, split hi/lo
#pragma unroll
        for (int i = 0; i < 4; i++) {
            int idx = tid + i * 256;
            int k = idx >> 5, cq = idx & 31;
            float4 v = *(const float4*)&Bb[(size_t)(k0 + k) * 128 + cq * 4];
            float4 h, l;
            h.x = tf32r(v.x); l.x = tf32r(v.x - h.x);
            h.y = tf32r(v.y); l.y = tf32r(v.y - h.y);
            h.z = tf32r(v.z); l.z = tf32r(v.z - h.z);
            h.w = tf32r(v.w); l.w = tf32r(v.w - h.w);
            *(float4*)&Bh[k * BSTRIDE + cq * 4] = h;
            *(float4*)&Bl[k * BSTRIDE + cq * 4] = l;
        }
        __syncthreads();

#pragma unroll
        for (int ks = 0; ks < 4; ks++) {
            const int kk = ks << 3;
            uint32_t ah[4][4], al[4][4];
#pragma unroll
            for (int fm = 0; fm < 4; fm++) {
                const float* pa = &Ah[(wm + fm * 16 + r) * ASTRIDE + kk + cc];
                const float* pl = &Al[(wm + fm * 16 + r) * ASTRIDE + kk + cc];
                ah[fm][0] = __float_as_uint(pa[0]);
                ah[fm][1] = __float_as_uint(pa[8 * ASTRIDE]);
                ah[fm][2] = __float_as_uint(pa[4]);
                ah[fm][3] = __float_as_uint(pa[8 * ASTRIDE + 4]);
                al[fm][0] = __float_as_uint(pl[0]);
                al[fm][1] = __float_as_uint(pl[8 * ASTRIDE]);
                al[fm][2] = __float_as_uint(pl[4]);
                al[fm][3] = __float_as_uint(pl[8 * ASTRIDE + 4]);
            }
#pragma unroll
            for (int fn = 0; fn < 4; fn++) {
                const int nb = wn + fn * 8 + r;
                const int kb = kk + cc;
                uint32_t b0h = __float_as_uint(Bh[kb * BSTRIDE + nb]);
                uint32_t b1h = __float_as_uint(Bh[(kb + 4) * BSTRIDE + nb]);
                uint32_t b0l = __float_as_uint(Bl[kb * BSTRIDE + nb]);
                uint32_t b1l = __float_as_uint(Bl[(kb + 4) * BSTRIDE + nb]);
#pragma unroll
                for (int fm = 0; fm < 4; fm++) {
                    MMA_TF32(acc[fm][fn], ah[fm], b0h, b1h);
                    MMA_TF32(acc[fm][fn], ah[fm], b0l, b1l);
                    MMA_TF32(acc[fm][fn], al[fm], b0h, b1h);
                }
            }
        }
        __syncthreads();
    }

    // epilogue
#pragma unroll
    for (int fm = 0; fm < 4; fm++) {
        int m = wm + fm * 16 + r;
#pragma unroll
        for (int fn = 0; fn < 4; fn++) {
            int col = wn + fn * 8 + cc * 2;
            *(float2*)&Cb[(size_t)m * 128 + col] =
                make_float2(acc[fm][fn][0], acc[fm][fn][1]);
            *(float2*)&Cb[(size_t)(m + 8) * 128 + col] =
                make_float2(acc[fm][fn][2], acc[fm][fn][3]);
        }
    }
}

// ---------------- other kernels ----------------

__global__ void k_deg(const int* __restrict__ dst, int E) {
    int e = blockIdx.x * blockDim.x + threadIdx.x;
    if (e < E) atomicAdd(&g_deg[dst[e]], 1);
}

__global__ void k_scan(int eper) {
    __shared__ int sh[NN];
    int g = blockIdx.x, i = threadIdx.x;
    int n = g * NN + i;
    int d = g_deg[n];
    g_deg[n] = 0;
    g_dinv1[n] = rsqrtf((float)d + 1.0f);
    g_dinv2[n] = d > 0 ? rsqrtf((float)d) : 0.0f;
    sh[i] = d; __syncthreads();
#pragma unroll
    for (int off = 1; off < NN; off <<= 1) {
        int v = (i >= off) ? sh[i - off] : 0;
        __syncthreads();
        sh[i] += v;
        __syncthreads();
    }
    int o = g * eper + sh[i] - d;
    g_offs[n] = o;
    g_cur[n] = o;
}

__global__ void k_fill(const int* __restrict__ src, const int* __restrict__ dst, int E) {
    int e = blockIdx.x * blockDim.x + threadIdx.x;
    if (e >= E) return;
    int pos = atomicAdd(&g_cur[dst[e]], 1);
    g_csr[pos] = src[e];
}

__global__ void k_agg1(const float* __restrict__ feat, const float* __restrict__ bias,
                       float* __restrict__ out)
{
    int n = (blockIdx.x * blockDim.x + threadIdx.x) >> 5;
    if (n >= NT) return;
    int lane = threadIdx.x & 31;
    int e0 = g_offs[n], e1 = g_cur[n];
    float dd = g_dinv1[n];
    float ax = 0.f, ay = 0.f, az = 0.f, aw = 0.f;
    for (int e = e0; e < e1; e++) {
        int s = g_csr[e];
        float c = g_dinv1[s] * dd;
        float4 v = ((const float4*)feat)[(size_t)s * 32 + lane];
        ax += v.x * c; ay += v.y * c; az += v.z * c; aw += v.w * c;
    }
    float4 hv = ((const float4*)feat)[(size_t)n * 32 + lane];
    float sc = dd * dd;
    float4 b4 = ((const float4*)bias)[lane];
    float4 o;
    o.x = fmaxf(ax + hv.x * sc + b4.x, 0.f);
    o.y = fmaxf(ay + hv.y * sc + b4.y, 0.f);
    o.z = fmaxf(az + hv.z * sc + b4.z, 0.f);
    o.w = fmaxf(aw + hv.w * sc + b4.w, 0.f);
    ((float4*)out)[(size_t)n * 32 + lane] = o;
}

__global__ void k_aggscore(const float* __restrict__ feat)
{
    int n = (blockIdx.x * blockDim.x + threadIdx.x) >> 5;
    if (n >= NT) return;
    int lane = threadIdx.x & 31;
    int e0 = g_offs[n], e1 = g_cur[n];
    float dd = g_dinv2[n];
    float ax = 0.f, ay = 0.f, az = 0.f, aw = 0.f;
    for (int e = e0; e < e1; e++) {
        int s = g_csr[e];
        float c = g_dinv2[s] * dd;
        float4 v = ((const float4*)feat)[(size_t)s * 32 + lane];
        ax += v.x * c; ay += v.y * c; az += v.z * c; aw += v.w * c;
    }
    float4 hv = ((const float4*)feat)[(size_t)n * 32 + lane];
    float s = fabsf(hv.x - ax) + fabsf(hv.y - ay) + fabsf(hv.z - az) + fabsf(hv.w - aw);
#pragma unroll
    for (int o = 16; o > 0; o >>= 1) s += __shfl_down_sync(0xffffffffu, s, o);
    if (lane == 0) g_s1[n] = s;
}

__global__ void k_topk(const float* __restrict__ scores, int n, int k,
                       int* __restrict__ idx_out, int* __restrict__ keep)
{
    extern __shared__ float ss[];
    int g = blockIdx.x, i = threadIdx.x;
    float si = scores[(size_t)g * n + i];
    ss[i] = si;
    __syncthreads();
    int rank = 0;
    for (int j = 0; j < n; j++) {
        float sj = ss[j];
        rank += (sj > si) || (sj == si && j < i);
    }
    if (rank < k) idx_out[(size_t)g * k + rank] = i;
    if (keep) keep[(size_t)g * n + i] = (rank < k) ? rank : -1;
}

__global__ void k_gather(const float* __restrict__ src, const int* __restrict__ idx,
                         float* __restrict__ dst, int rowsPerG, int k)
{
    int w = (blockIdx.x * blockDim.x + threadIdx.x) >> 5;
    if (w >= BB * k) return;
    int lane = threadIdx.x & 31;
    int g = w / k;
    int i = idx[w];
    ((float4*)(dst + (size_t)w * HH))[lane] =
        ((const float4*)(src + ((size_t)g * rowsPerG + i) * HH))[lane];
}

__global__ void k_edgeAk(const int* __restrict__ src, const int* __restrict__ dst, int E) {
    int e = blockIdx.x * blockDim.x + threadIdx.x;
    if (e >= E) return;
    int s = src[e];
    int rs = g_keep[s];
    if (rs < 0) return;
    int d = dst[e];
    int rd = g_keep[d];
    if (rd < 0) return;
    int g = s >> 9;
    atomicAdd(&g_Akb[((size_t)g * K1 + rs) * K1 + rd], 1.0f);
}

__global__ void k_qs(const float* __restrict__ feat, const float* __restrict__ att,
                     float* __restrict__ q, float* __restrict__ s, int rows)
{
    int w = (blockIdx.x * blockDim.x + threadIdx.x) >> 5;
    if (w >= rows) return;
    int lane = threadIdx.x & 31;
    float4 h4 = ((const float4*)(feat + (size_t)w * HH))[lane];
    float4 a4 = ((const float4*)att)[lane];
    float4 b4 = ((const float4*)att)[32 + lane];
    float qd = h4.x*a4.x + h4.y*a4.y + h4.z*a4.z + h4.w*a4.w;
    float sd = h4.x*b4.x + h4.y*b4.y + h4.z*b4.z + h4.w*b4.w;
#pragma unroll
    for (int o = 16; o > 0; o >>= 1) {
        qd += __shfl_down_sync(0xffffffffu, qd, o);
        sd += __shfl_down_sync(0xffffffffu, sd, o);
    }
    if (lane == 0) { q[w] = qd; s[w] = sd; }
}

template <int KDIM, int MODE>
__global__ void k_struct() {
    int row = blockIdx.x;
    int g = row / KDIM;
    int j = threadIdx.x;
    __shared__ float red[KDIM];
    float qi = (MODE == 0 ? g_q1 : g_q2)[row];
    float sj = (MODE == 0 ? g_sv1 : g_sv2)[(size_t)g * KDIM + j];
    float v = qi + sj;
    v = v > 0.f ? v : 0.2f * v;
    red[j] = v; __syncthreads();
    for (int st = KDIM / 2; st > 0; st >>= 1) {
        if (j < st) red[j] = fmaxf(red[j], red[j + st]);
        __syncthreads();
    }
    float vmax = red[0]; __syncthreads();
    float e = __expf(v - vmax);
    red[j] = e; __syncthreads();
    for (int st = KDIM / 2; st > 0; st >>= 1) {
        if (j < st) red[j] += red[j + st];
        __syncthreads();
    }
    float esum = red[0]; __syncthreads();
    float ak;
    if (MODE == 0) {
        size_t off = (size_t)row * K1 + j;
        ak = g_Akb[off];
        g_Akb[off] = 0.f;
    } else {
        int ig = g_idx2[row];
        int jg = g_idx2[g * K2 + j];
        ak = g_A1[((size_t)g * K1 + ig) * K1 + jg];
    }
    (MODE == 0 ? g_A1 : g_A2)[(size_t)row * KDIM + j] = e / esum + ak;
    red[j] = ak; __syncthreads();
    for (int st = KDIM / 2; st > 0; st >>= 1) {
        if (j < st) red[j] += red[j + st];
        __syncthreads();
    }
    if (j == 0) (MODE == 0 ? g_rowA1 : g_rowA2)[row] = red[0];
}

__global__ void k_readout(const float* __restrict__ feat, int k, float* __restrict__ out, int accumulate) {
    int g = blockIdx.x, f = threadIdx.x;
    float mx = -1e30f, sm = 0.f;
    const float* p = feat + (size_t)g * k * HH + f;
    for (int n = 0; n < k; n++) {
        float v = p[(size_t)n * HH];
        mx = fmaxf(mx, v);
        sm += v;
    }
    float o0 = fmaxf(mx, 0.f);
    float o1 = fmaxf(sm / (float)k, 0.f);
    if (accumulate) { out[g * 256 + f] += o0; out[g * 256 + 128 + f] += o1; }
    else            { out[g * 256 + f]  = o0; out[g * 256 + 128 + f]  = o1; }
}

__global__ void k_scale_copy(const float* __restrict__ src, float* __restrict__ dst,
                             const float* __restrict__ rowA, float add, size_t total) {
    size_t idx = (size_t)blockIdx.x * blockDim.x + threadIdx.x;
    if (idx >= total) return;
    int row = (int)(idx >> 7);
    float d = rsqrtf(fmaxf(rowA[row] + add, 1e-12f));
    dst[idx] = src[idx] * d;
}

__global__ void k_combine2(const float* __restrict__ tmp, const float* __restrict__ hws,
                           const float* __restrict__ rowA, const float* __restrict__ bias,
                           float* __restrict__ out, size_t total) {
    size_t idx = (size_t)blockIdx.x * blockDim.x + threadIdx.x;
    if (idx >= total) return;
    int row = (int)(idx >> 7), f = (int)(idx & 127);
    float di = rsqrtf(fmaxf(rowA[row] + 2.0f, 1e-12f));
    out[idx] = fmaxf(di * (tmp[idx] + hws[idx]) + bias[f], 0.f);
}

__global__ void k_score2(const float* __restrict__ h2, const float* __restrict__ tmp2,
                         const float* __restrict__ rowA, float* __restrict__ sc, int rows) {
    int w = (blockIdx.x * blockDim.x + threadIdx.x) >> 5;
    if (w >= rows) return;
    int lane = threadIdx.x & 31;
    float d = rsqrtf(fmaxf(rowA[w] + 1.0f, 1e-12f));
    size_t base = (size_t)w * HH + lane * 4;
    float4 hv = *(const float4*)&h2[base];
    float4 tv = *(const float4*)&tmp2[base];
    float s = fabsf(hv.x - d*tv.x) + fabsf(hv.y - d*tv.y) + fabsf(hv.z - d*tv.z) + fabsf(hv.w - d*tv.w);
#pragma unroll
    for (int o = 16; o > 0; o >>= 1) s += __shfl_down_sync(0xffffffffu, s, o);
    if (lane == 0) sc[w] = s;
}

// ---------------- host ----------------

static float* symf(const void* sym) {
    void* p = nullptr;
    cudaGetSymbolAddress(&p, sym);
    return (float*)p;
}
static int* symi(const void* sym) {
    void* p = nullptr;
    cudaGetSymbolAddress(&p, sym);
    return (int*)p;
}

extern "C" void kernel_launch(void* const* d_in, const int* in_sizes, int n_in,
                              void* d_out, int out_size)
{
    const float* x    = (const float*)d_in[0];
    const float* W1   = (const float*)d_in[1];
    const float* b1   = (const float*)d_in[2];
    const float* W2   = (const float*)d_in[3];
    const float* b2   = (const float*)d_in[4];
    const float* W3   = (const float*)d_in[5];
    const float* b3   = (const float*)d_in[6];
    const float* att1 = (const float*)d_in[7];
    const float* att2 = (const float*)d_in[8];
    const int* esrc   = (const int*)d_in[9];
    const int* edst   = (const int*)d_in[10];
    int E = in_sizes[9];
    int eper = E / BB;
    float* out = (float*)d_out;

    static int smem_set = 0;
    if (!smem_set) {
        cudaFuncSetAttribute(k_gemm_mma, cudaFuncAttributeMaxDynamicSharedMemorySize, GEMM_SMEM);
        smem_set = 1;
    }

    float* p_h    = symf(g_h);
    float* p_hr   = symf(g_hr);
    float* p_s1   = symf(g_s1);
    int*   p_idx1 = symi(g_idx1);
    int*   p_keep = symi(g_keep);
    float* p_hk   = symf(g_hk);
    float* p_A1   = symf(g_A1);
    float* p_q1   = symf(g_q1);
    float* p_sv1  = symf(g_sv1);
    float* p_rA1  = symf(g_rowA1);
    float* p_hw   = symf(g_hw);
    float* p_tmp  = symf(g_tmp);
    float* p_h2   = symf(g_h2);
    float* p_h2s  = symf(g_h2s);
    float* p_tmp2 = symf(g_tmp2);
    float* p_s2   = symf(g_s2);
    int*   p_idx2 = symi(g_idx2);
    float* p_h2k  = symf(g_h2k);
    float* p_A2   = symf(g_A2);
    float* p_q2   = symf(g_q2);
    float* p_sv2  = symf(g_sv2);
    float* p_rA2  = symf(g_rowA2);
    float* p_hw3  = symf(g_hw3);
    float* p_tmp3 = symf(g_tmp3);
    float* p_h3   = symf(g_h3);

    const size_t T2 = (size_t)BB * K1 * HH;
    const size_t T3 = (size_t)BB * K2 * HH;

    // ---- stage 1: CSR build + edge GCN + info score ----
    k_deg<<<(E + 255) / 256, 256>>>(edst, E);
    k_gemm_mma<<<dim3(1, NT / 128, 1), 256, GEMM_SMEM>>>(x, W1, p_h, NT, FF, 0, 0, 0);
    k_scan<<<BB, NN>>>(eper);
    k_fill<<<(E + 255) / 256, 256>>>(esrc, edst, E);
    k_agg1<<<(NT * 32 + 255) / 256, 256>>>(p_h, b1, p_hr);
    k_aggscore<<<(NT * 32 + 255) / 256, 256>>>(p_hr);

    // ---- pool 1 ----
    k_topk<<<BB, NN, NN * sizeof(float)>>>(p_s1, NN, K1, p_idx1, p_keep);
    k_gather<<<(BB * K1 * 32 + 255) / 256, 256>>>(p_hr, p_idx1, p_hk, NN, K1);
    k_edgeAk<<<(E + 255) / 256, 256>>>(esrc, edst, E);
    k_qs<<<(BB * K1 * 32 + 255) / 256, 256>>>(p_hk, att1, p_q1, p_sv1, BB * K1);
    k_struct<K1, 0><<<BB * K1, K1>>>();
    k_readout<<<BB, 128>>>(p_hk, K1, out, 0);

    // ---- conv2 (dense GCN on A1) ----
    k_gemm_mma<<<dim3(1, K1 / 128, BB), 256, GEMM_SMEM>>>(p_hk, W2, p_hw, K1, HH,
                                             (long long)K1 * HH, 0, (long long)K1 * HH);
    k_scale_copy<<<(unsigned)((T2 + 255) / 256), 256>>>(p_hw, p_hw, p_rA1, 2.0f, T2);
    k_gemm_mma<<<dim3(1, K1 / 128, BB), 256, GEMM_SMEM>>>(p_A1, p_hw, p_tmp, K1, K1,
                                             (long long)K1 * K1, (long long)K1 * HH, (long long)K1 * HH);
    k_combine2<<<(unsigned)((T2 + 255) / 256), 256>>>(p_tmp, p_hw, p_rA1, b2, p_h2, T2);

    // ---- info score 2 ----
    k_scale_copy<<<(unsigned)((T2 + 255) / 256), 256>>>(p_h2, p_h2s, p_rA1, 1.0f, T2);
    k_gemm_mma<<<dim3(1, K1 / 128, BB), 256, GEMM_SMEM>>>(p_A1, p_h2s, p_tmp2, K1, K1,
                                             (long long)K1 * K1, (long long)K1 * HH, (long long)K1 * HH);
    k_score2<<<(BB * K1 * 32 + 255) / 256, 256>>>(p_h2, p_tmp2, p_rA1, p_s2, BB * K1);

    // ---- pool 2 ----
    k_topk<<<BB, K1, K1 * sizeof(float)>>>(p_s2, K1, K2, p_idx2, nullptr);
    k_gather<<<(BB * K2 * 32 + 255) / 256, 256>>>(p_h2, p_idx2, p_h2k, K1, K2);
    k_qs<<<(BB * K2 * 32 + 255) / 256, 256>>>(p_h2k, att2, p_q2, p_sv2, BB * K2);
    k_struct<K2, 1><<<BB * K2, K2>>>();
    k_readout<<<BB, 128>>>(p_h2k, K2, out, 1);

    // ---- conv3 ----
    k_gemm_mma<<<dim3(1, K2 / 128, BB), 256, GEMM_SMEM>>>(p_h2k, W3, p_hw3, K2, HH,
                                             (long long)K2 * HH, 0, (long long)K2 * HH);
    k_scale_copy<<<(unsigned)((T3 + 255) / 256), 256>>>(p_hw3, p_hw3, p_rA2, 2.0f, T3);
    k_gemm_mma<<<dim3(1, K2 / 128, BB), 256, GEMM_SMEM>>>(p_A2, p_hw3, p_tmp3, K2, K2,
                                             (long long)K2 * K2, (long long)K2 * HH, (long long)K2 * HH);
    k_combine2<<<(unsigned)((T3 + 255) / 256), 256>>>(p_tmp3, p_hw3, p_rA2, b3, p_h3, T3);
    k_readout<<<BB, 128>>>(p_h3, K2, out, 1);
}